// round 1
// baseline (speedup 1.0000x reference)
#include <cuda_runtime.h>

#define N_USERS 50000
#define N_ENT   150000
#define NN      200000   // N_USERS + N_ENT
#define EE      2000000
#define BB      8192

// ---------------------------------------------------------------------------
// Device-global scratch (allocation-free rule: __device__ arrays)
// ---------------------------------------------------------------------------
__device__ float g_E0[(size_t)NN * 64];  // embs[0]  (initial ego, 64)
__device__ float g_A [(size_t)NN * 64];  // ping
__device__ float g_Bu[(size_t)NN * 64];  // pong
__device__ float g_S [(size_t)NN * 64];  // side (segment sum)
__device__ float g_N1[(size_t)NN * 64];  // l2norm(ego after layer 0)
__device__ float g_N2[(size_t)NN * 32];  // l2norm(ego after layer 1)
__device__ float g_N3[(size_t)NN * 16];  // l2norm(ego after layer 2)

__device__ __forceinline__ float* buf(int id) {
    switch (id) {
        case 0:  return g_E0;
        case 1:  return g_A;
        case 2:  return g_Bu;
        case 3:  return g_N1;
        case 4:  return g_N2;
        default: return g_N3;
    }
}

__device__ __forceinline__ float leaky(float x) {
    return x >= 0.f ? x : 0.01f * x;
}

// ---------------------------------------------------------------------------
// Init: ego = concat(user_embed, entity_embed)  (float4 copies)
// ---------------------------------------------------------------------------
__global__ void init_ego(const float4* __restrict__ ue, const float4* __restrict__ ee) {
    int i = blockIdx.x * blockDim.x + threadIdx.x;
    const int nu4  = N_USERS * 16;   // 64 floats / 4
    const int tot4 = NN * 16;
    if (i < nu4)       ((float4*)g_E0)[i] = ue[i];
    else if (i < tot4) ((float4*)g_E0)[i] = ee[i - nu4];
}

// ---------------------------------------------------------------------------
// Zero the side buffer (n4 = #float4)
// ---------------------------------------------------------------------------
__global__ void zero_side(int n4) {
    int i = blockIdx.x * blockDim.x + threadIdx.x;
    if (i < n4) ((float4*)g_S)[i] = make_float4(0.f, 0.f, 0.f, 0.f);
}

// ---------------------------------------------------------------------------
// Edge scatter: side[row] += val * ego[col].   One warp per edge.
// ---------------------------------------------------------------------------
template <int DIN>
__global__ void scatter_edges(const int* __restrict__ rows,
                              const int* __restrict__ cols,
                              const float* __restrict__ vals,
                              int ego_id) {
    int t    = blockIdx.x * blockDim.x + threadIdx.x;
    int w    = t >> 5;
    int lane = t & 31;
    if (w >= EE) return;

    const float* ego = buf(ego_id);
    int   r = rows[w];
    int   c = cols[w];
    float v = vals[w];

    if (DIN == 64) {
        float2 e = ((const float2*)(ego + (size_t)c * 64))[lane];
        float  x = e.x * v, y = e.y * v;
        float* dst = g_S + (size_t)r * 64 + lane * 2;
        asm volatile("red.global.add.v2.f32 [%0], {%1, %2};"
                     :: "l"(dst), "f"(x), "f"(y) : "memory");
    } else {  // DIN == 32
        float e = ego[(size_t)c * 32 + lane];
        float* dst = g_S + (size_t)r * 32 + lane;
        asm volatile("red.global.add.f32 [%0], %1;"
                     :: "l"(dst), "f"(e * v) : "memory");
    }
}

// ---------------------------------------------------------------------------
// Fused transform: per node
//   h1 = ego + side ; h2 = ego * side
//   ego' = leaky(h1 @ Wg + bg) + leaky(h2 @ Wb + bb)
//   write ego' (raw) and l2norm(ego')
// One warp per row; weights + biases staged in shared memory.
// ---------------------------------------------------------------------------
template <int DIN, int DOUT>
__global__ void transform_nodes(int ego_id,
                                const float* __restrict__ Wg, const float* __restrict__ bg,
                                const float* __restrict__ Wb, const float* __restrict__ bb,
                                int raw_id, int norm_id) {
    __shared__ float sWg[DIN * DOUT];
    __shared__ float sWb[DIN * DOUT];
    __shared__ float sbg[DOUT];
    __shared__ float sbb[DOUT];
    __shared__ float sh1[8][DIN];
    __shared__ float sh2[8][DIN];

    int tid = threadIdx.x;
    for (int i = tid; i < DIN * DOUT; i += 256) { sWg[i] = Wg[i]; sWb[i] = Wb[i]; }
    for (int i = tid; i < DOUT; i += 256)       { sbg[i] = bg[i]; sbb[i] = bb[i]; }
    __syncthreads();

    int w    = tid >> 5;
    int lane = tid & 31;
    int row  = blockIdx.x * 8 + w;
    if (row >= NN) return;

    const float* ego  = buf(ego_id)  + (size_t)row * DIN;
    const float* side = g_S          + (size_t)row * DIN;
    float* oraw  = buf(raw_id)  + (size_t)row * DOUT;
    float* onorm = buf(norm_id) + (size_t)row * DOUT;

    #pragma unroll
    for (int t = lane; t < DIN; t += 32) {
        float e = ego[t], s = side[t];
        sh1[w][t] = e + s;
        sh2[w][t] = e * s;
    }
    __syncwarp();

    constexpr int JR = (DOUT + 31) / 32;
    float accg[JR], accb[JR];
    #pragma unroll
    for (int j = 0; j < JR; j++) {
        int ji = j * 32 + lane;
        accg[j] = (ji < DOUT) ? sbg[ji] : 0.f;
        accb[j] = (ji < DOUT) ? sbb[ji] : 0.f;
    }

    #pragma unroll 8
    for (int k = 0; k < DIN; k++) {
        float a = sh1[w][k];
        float b = sh2[w][k];
        #pragma unroll
        for (int j = 0; j < JR; j++) {
            int ji = j * 32 + lane;
            if (ji < DOUT) {
                accg[j] += a * sWg[k * DOUT + ji];
                accb[j] += b * sWb[k * DOUT + ji];
            }
        }
    }

    float o[JR];
    float ss = 0.f;
    #pragma unroll
    for (int j = 0; j < JR; j++) {
        int ji = j * 32 + lane;
        float x = 0.f;
        if (ji < DOUT) x = leaky(accg[j]) + leaky(accb[j]);
        o[j] = x;
        ss += x * x;
    }
    #pragma unroll
    for (int off = 16; off > 0; off >>= 1)
        ss += __shfl_xor_sync(0xffffffffu, ss, off);
    float inv = 1.0f / fmaxf(sqrtf(ss), 1e-12f);

    #pragma unroll
    for (int j = 0; j < JR; j++) {
        int ji = j * 32 + lane;
        if (ji < DOUT) {
            oraw[ji]  = o[j];
            onorm[ji] = o[j] * inv;
        }
    }
}

// ---------------------------------------------------------------------------
// Final scoring: one warp per batch element.
// all_emb = [E0(64) | N1(64) | N2(32) | N3(16)]   (176 dims)
// ---------------------------------------------------------------------------
__global__ void final_score(const int* __restrict__ users,
                            const int* __restrict__ pos,
                            const int* __restrict__ neg,
                            float* __restrict__ out) {
    int t    = blockIdx.x * blockDim.x + threadIdx.x;
    int w    = t >> 5;
    int lane = t & 31;
    if (w >= BB) return;

    int u = users[w];
    int p = N_USERS + pos[w];
    int n = N_USERS + neg[w];

    float sp = 0.f, sn = 0.f;

    #pragma unroll
    for (int j = 0; j < 2; j++) {
        int k = j * 32 + lane;
        float au = g_E0[(size_t)u * 64 + k];
        float ap = g_E0[(size_t)p * 64 + k];
        float an = g_E0[(size_t)n * 64 + k];
        sp += au * ap; sn += au * an;
    }
    #pragma unroll
    for (int j = 0; j < 2; j++) {
        int k = j * 32 + lane;
        float au = g_N1[(size_t)u * 64 + k];
        float ap = g_N1[(size_t)p * 64 + k];
        float an = g_N1[(size_t)n * 64 + k];
        sp += au * ap; sn += au * an;
    }
    {
        float au = g_N2[(size_t)u * 32 + lane];
        float ap = g_N2[(size_t)p * 32 + lane];
        float an = g_N2[(size_t)n * 32 + lane];
        sp += au * ap; sn += au * an;
    }
    if (lane < 16) {
        float au = g_N3[(size_t)u * 16 + lane];
        float ap = g_N3[(size_t)p * 16 + lane];
        float an = g_N3[(size_t)n * 16 + lane];
        sp += au * ap; sn += au * an;
    }

    #pragma unroll
    for (int off = 16; off > 0; off >>= 1) {
        sp += __shfl_xor_sync(0xffffffffu, sp, off);
        sn += __shfl_xor_sync(0xffffffffu, sn, off);
    }
    if (lane == 0) {
        out[(size_t)w * 2 + 0] = sp;
        out[(size_t)w * 2 + 1] = sn;
    }
}

// ---------------------------------------------------------------------------
// Launch
// ---------------------------------------------------------------------------
extern "C" void kernel_launch(void* const* d_in, const int* in_sizes, int n_in,
                              void* d_out, int out_size) {
    const int*   users = (const int*)  d_in[0];
    const int*   pos   = (const int*)  d_in[1];
    const int*   neg   = (const int*)  d_in[2];
    const int*   rows  = (const int*)  d_in[3];
    const int*   cols  = (const int*)  d_in[4];
    const float* vals  = (const float*)d_in[5];
    const float* ue    = (const float*)d_in[6];
    const float* ee    = (const float*)d_in[7];
    const float* Wg0 = (const float*)d_in[8],  *bg0 = (const float*)d_in[9];
    const float* Wb0 = (const float*)d_in[10], *bb0 = (const float*)d_in[11];
    const float* Wg1 = (const float*)d_in[12], *bg1 = (const float*)d_in[13];
    const float* Wb1 = (const float*)d_in[14], *bb1 = (const float*)d_in[15];
    const float* Wg2 = (const float*)d_in[16], *bg2 = (const float*)d_in[17];
    const float* Wb2 = (const float*)d_in[18], *bb2 = (const float*)d_in[19];
    float* out = (float*)d_out;

    // init ego = concat(user_embed, entity_embed)
    {
        int tot4 = NN * 16;
        init_ego<<<(tot4 + 255) / 256, 256>>>((const float4*)ue, (const float4*)ee);
    }

    const int scatter_blocks = (EE * 32 + 255) / 256;
    const int node_blocks    = (NN + 7) / 8;

    // ---- Layer 0: 64 -> 64   (in: E0[0], out raw: A[1], norm: N1[3]) ----
    zero_side<<<(NN * 16 + 255) / 256, 256>>>(NN * 16);
    scatter_edges<64><<<scatter_blocks, 256>>>(rows, cols, vals, 0);
    transform_nodes<64, 64><<<node_blocks, 256>>>(0, Wg0, bg0, Wb0, bb0, 1, 3);

    // ---- Layer 1: 64 -> 32   (in: A[1], out raw: Bu[2], norm: N2[4]) ----
    zero_side<<<(NN * 16 + 255) / 256, 256>>>(NN * 16);
    scatter_edges<64><<<scatter_blocks, 256>>>(rows, cols, vals, 1);
    transform_nodes<64, 32><<<node_blocks, 256>>>(1, Wg1, bg1, Wb1, bb1, 2, 4);

    // ---- Layer 2: 32 -> 16   (in: Bu[2], out raw: A[1] (unused), norm: N3[5]) ----
    zero_side<<<(NN * 8 + 255) / 256, 256>>>(NN * 8);
    scatter_edges<32><<<scatter_blocks, 256>>>(rows, cols, vals, 2);
    transform_nodes<32, 16><<<node_blocks, 256>>>(2, Wg2, bg2, Wb2, bb2, 1, 5);

    // ---- Final scoring ----
    final_score<<<(BB * 32 + 255) / 256, 256>>>(users, pos, neg, out);
}

// round 2
// speedup vs baseline: 2.1792x; 2.1792x over previous
#include <cuda_runtime.h>

#define N_USERS 50000
#define N_ENT   150000
#define NN      200000   // N_USERS + N_ENT
#define EE      2000000
#define BB      8192
#define CHUNK   1024
#define NBLK    ((NN + CHUNK - 1) / CHUNK)   // 196

// ---------------------------------------------------------------------------
// Device-global scratch (allocation-free rule: __device__ arrays)
// ---------------------------------------------------------------------------
__device__ float g_E0[(size_t)NN * 64];  // embs[0]  (initial ego, 64)
__device__ float g_A [(size_t)NN * 64];  // ping
__device__ float g_Bu[(size_t)NN * 64];  // pong
__device__ float g_S [(size_t)NN * 64];  // side (segment sum result)
__device__ float g_N1[(size_t)NN * 64];  // l2norm after layer 0
__device__ float g_N2[(size_t)NN * 32];  // l2norm after layer 1
__device__ float g_N3[(size_t)NN * 16];  // l2norm after layer 2

// CSR structures
__device__ int    g_cnt[NN];         // histogram, then permute cursor
__device__ int    g_rowptr[NN + 1];
__device__ int    g_bsum[NBLK];
__device__ int    g_boff[NBLK];
__device__ float2 g_edges[EE];       // packed (col_as_float_bits, val)

__device__ __forceinline__ float* buf(int id) {
    switch (id) {
        case 0:  return g_E0;
        case 1:  return g_A;
        case 2:  return g_Bu;
        case 3:  return g_N1;
        case 4:  return g_N2;
        default: return g_N3;
    }
}

__device__ __forceinline__ float leaky(float x) {
    return x >= 0.f ? x : 0.01f * x;
}

// packed f32x2 helpers
__device__ __forceinline__ unsigned long long pk2(float x, float y) {
    unsigned long long r;
    asm("mov.b64 %0, {%1, %2};" : "=l"(r) : "f"(x), "f"(y));
    return r;
}
__device__ __forceinline__ void upk2(unsigned long long v, float& x, float& y) {
    asm("mov.b64 {%0, %1}, %2;" : "=f"(x), "=f"(y) : "l"(v));
}
__device__ __forceinline__ unsigned long long f2fma(unsigned long long a,
                                                    unsigned long long b,
                                                    unsigned long long c) {
    unsigned long long d;
    asm("fma.rn.f32x2 %0, %1, %2, %3;" : "=l"(d) : "l"(a), "l"(b), "l"(c));
    return d;
}

// ---------------------------------------------------------------------------
// Init: ego = concat(user_embed, entity_embed)
// ---------------------------------------------------------------------------
__global__ void init_ego(const float4* __restrict__ ue, const float4* __restrict__ ee) {
    int i = blockIdx.x * blockDim.x + threadIdx.x;
    const int nu4  = N_USERS * 16;
    const int tot4 = NN * 16;
    if (i < nu4)       ((float4*)g_E0)[i] = ue[i];
    else if (i < tot4) ((float4*)g_E0)[i] = ee[i - nu4];
}

// ---------------------------------------------------------------------------
// CSR build
// ---------------------------------------------------------------------------
__global__ void zero_cnt() {
    int i = blockIdx.x * blockDim.x + threadIdx.x;
    if (i < NN) g_cnt[i] = 0;
}

__global__ void hist(const int* __restrict__ rows) {
    int e = blockIdx.x * blockDim.x + threadIdx.x;
    if (e < EE) atomicAdd(&g_cnt[rows[e]], 1);
}

// per-chunk exclusive scan (chunk = 1024, block = 256, 4 elems/thread)
__global__ void scan1() {
    __shared__ int sh[256];
    int b = blockIdx.x, t = threadIdx.x;
    int base = b * CHUNK + t * 4;
    int v[4]; int s = 0;
    #pragma unroll
    for (int j = 0; j < 4; j++) {
        int idx = base + j;
        v[j] = (idx < NN) ? g_cnt[idx] : 0;
        s += v[j];
    }
    sh[t] = s;
    __syncthreads();
    for (int off = 1; off < 256; off <<= 1) {
        int x = (t >= off) ? sh[t - off] : 0;
        __syncthreads();
        sh[t] += x;
        __syncthreads();
    }
    int excl = sh[t] - s;
    #pragma unroll
    for (int j = 0; j < 4; j++) {
        int idx = base + j;
        if (idx < NN) g_rowptr[idx] = excl;
        excl += v[j];
    }
    if (t == 255) g_bsum[b] = sh[255];
}

__global__ void scan2() {
    __shared__ int sh[256];
    int t = threadIdx.x;
    int v = (t < NBLK) ? g_bsum[t] : 0;
    sh[t] = v;
    __syncthreads();
    for (int off = 1; off < 256; off <<= 1) {
        int x = (t >= off) ? sh[t - off] : 0;
        __syncthreads();
        sh[t] += x;
        __syncthreads();
    }
    if (t < NBLK) g_boff[t] = sh[t] - v;
}

// add block offsets; also init permute cursor (g_cnt = rowptr) and rowptr[NN]
__global__ void scan3() {
    int i = blockIdx.x * blockDim.x + threadIdx.x;
    if (i < NN) {
        int r = g_rowptr[i] + g_boff[i / CHUNK];
        g_rowptr[i] = r;
        g_cnt[i]    = r;
    }
    if (i == 0) g_rowptr[NN] = EE;
}

__global__ void permute(const int* __restrict__ rows, const int* __restrict__ cols,
                        const float* __restrict__ vals) {
    int e = blockIdx.x * blockDim.x + threadIdx.x;
    if (e < EE) {
        int r = rows[e];
        int p = atomicAdd(&g_cnt[r], 1);
        g_edges[p] = make_float2(__int_as_float(cols[e]), vals[e]);
    }
}

// ---------------------------------------------------------------------------
// SpMM gather: side[n] = sum_{e in row n} val_e * ego[col_e].  Warp per node.
// ---------------------------------------------------------------------------
template <int DIN>
__global__ void spmm_csr(int ego_id) {
    int t    = blockIdx.x * blockDim.x + threadIdx.x;
    int w    = t >> 5;
    int lane = t & 31;
    if (w >= NN) return;

    const float* ego = buf(ego_id);
    int start = g_rowptr[w];
    int end   = g_rowptr[w + 1];

    if (DIN == 64) {
        float2 acc = make_float2(0.f, 0.f);
        for (int e0 = start; e0 < end; e0 += 32) {
            int m = min(32, end - e0);
            float2 ev = make_float2(0.f, 0.f);
            if (lane < m) ev = g_edges[e0 + lane];
            for (int j = 0; j < m; j++) {
                int   c = __shfl_sync(0xffffffffu, __float_as_int(ev.x), j);
                float v = __shfl_sync(0xffffffffu, ev.y, j);
                float2 g = ((const float2*)(ego + (size_t)c * 64))[lane];
                acc.x += v * g.x;
                acc.y += v * g.y;
            }
        }
        ((float2*)(g_S + (size_t)w * 64))[lane] = acc;
    } else {  // DIN == 32
        float acc = 0.f;
        for (int e0 = start; e0 < end; e0 += 32) {
            int m = min(32, end - e0);
            float2 ev = make_float2(0.f, 0.f);
            if (lane < m) ev = g_edges[e0 + lane];
            for (int j = 0; j < m; j++) {
                int   c = __shfl_sync(0xffffffffu, __float_as_int(ev.x), j);
                float v = __shfl_sync(0xffffffffu, ev.y, j);
                acc += v * ego[(size_t)c * 32 + lane];
            }
        }
        g_S[(size_t)w * 32 + lane] = acc;
    }
}

// ---------------------------------------------------------------------------
// Transform as tiled block GEMM.  64 rows/block, 256 threads (16x16).
// Thread (ty,tx): rows ty*4..ty*4+3, cols tx*CPT..tx*CPT+CPT-1, CPT = DOUT/16.
//   h1 = ego+side; h2 = ego*side
//   out = leaky(h1@Wg + bg) + leaky(h2@Wb + bb);  write raw + l2norm
// ---------------------------------------------------------------------------
template <int DIN, int DOUT>
__global__ void transform_gemm(int ego_id,
                               const float* __restrict__ Wg, const float* __restrict__ bg,
                               const float* __restrict__ Wb, const float* __restrict__ bb,
                               int raw_id, int norm_id) {
    extern __shared__ float sm[];
    constexpr int LDA = DIN + 1;
    float* sA1 = sm;
    float* sA2 = sA1 + 64 * LDA;
    float* sWg = sA2 + 64 * LDA;
    float* sWb = sWg + DIN * DOUT;

    int tid = threadIdx.x;
    int R   = blockIdx.x * 64;
    const float* ego  = buf(ego_id) + (size_t)R * DIN;
    const float* side = g_S         + (size_t)R * DIN;

    for (int i = tid; i < DIN * DOUT; i += 256) { sWg[i] = Wg[i]; sWb[i] = Wb[i]; }
    for (int i = tid; i < 64 * DIN; i += 256) {
        int r = i / DIN, k = i - r * DIN;
        float e = ego[i];
        float s = side[i];
        sA1[r * LDA + k] = e + s;
        sA2[r * LDA + k] = e * s;
    }
    __syncthreads();

    int ty = tid >> 4, tx = tid & 15;
    constexpr int CPT = DOUT / 16;
    int colb = tx * CPT;

    float o[4][CPT];
    float ss[4] = {0.f, 0.f, 0.f, 0.f};

    if (CPT >= 2) {
        constexpr int C2 = (CPT >= 2) ? CPT / 2 : 1;
        unsigned long long accg[4][C2], accb[4][C2];
        #pragma unroll
        for (int c2 = 0; c2 < C2; c2++) {
            unsigned long long vg = pk2(bg[colb + 2 * c2], bg[colb + 2 * c2 + 1]);
            unsigned long long vb = pk2(bb[colb + 2 * c2], bb[colb + 2 * c2 + 1]);
            #pragma unroll
            for (int i = 0; i < 4; i++) { accg[i][c2] = vg; accb[i][c2] = vb; }
        }
        #pragma unroll 4
        for (int k = 0; k < DIN; k++) {
            unsigned long long pa1[4], pa2[4];
            #pragma unroll
            for (int i = 0; i < 4; i++) {
                float a1 = sA1[(ty * 4 + i) * LDA + k];
                float a2 = sA2[(ty * 4 + i) * LDA + k];
                pa1[i] = pk2(a1, a1);
                pa2[i] = pk2(a2, a2);
            }
            #pragma unroll
            for (int c2 = 0; c2 < C2; c2++) {
                unsigned long long wg = *(const unsigned long long*)(sWg + k * DOUT + colb + 2 * c2);
                unsigned long long wb = *(const unsigned long long*)(sWb + k * DOUT + colb + 2 * c2);
                #pragma unroll
                for (int i = 0; i < 4; i++) {
                    accg[i][c2] = f2fma(pa1[i], wg, accg[i][c2]);
                    accb[i][c2] = f2fma(pa2[i], wb, accb[i][c2]);
                }
            }
        }
        #pragma unroll
        for (int i = 0; i < 4; i++) {
            #pragma unroll
            for (int c2 = 0; c2 < C2; c2++) {
                float g0, g1, b0, b1;
                upk2(accg[i][c2], g0, g1);
                upk2(accb[i][c2], b0, b1);
                float x0 = leaky(g0) + leaky(b0);
                float x1 = leaky(g1) + leaky(b1);
                o[i][2 * c2]     = x0;
                o[i][2 * c2 + 1] = x1;
                ss[i] += x0 * x0 + x1 * x1;
            }
        }
    } else {
        // DOUT == 16 path (scalar)
        float accg[4], accb[4];
        float big = bg[colb], bib = bb[colb];
        #pragma unroll
        for (int i = 0; i < 4; i++) { accg[i] = big; accb[i] = bib; }
        #pragma unroll 4
        for (int k = 0; k < DIN; k++) {
            float wgv = sWg[k * DOUT + colb];
            float wbv = sWb[k * DOUT + colb];
            #pragma unroll
            for (int i = 0; i < 4; i++) {
                accg[i] += sA1[(ty * 4 + i) * LDA + k] * wgv;
                accb[i] += sA2[(ty * 4 + i) * LDA + k] * wbv;
            }
        }
        #pragma unroll
        for (int i = 0; i < 4; i++) {
            float x = leaky(accg[i]) + leaky(accb[i]);
            o[i][0] = x;
            ss[i] += x * x;
        }
    }

    // row-wise L2 norm across the 16-thread tx group (contiguous half-warp)
    #pragma unroll
    for (int off = 8; off > 0; off >>= 1) {
        #pragma unroll
        for (int i = 0; i < 4; i++)
            ss[i] += __shfl_xor_sync(0xffffffffu, ss[i], off, 16);
    }

    float* oraw  = buf(raw_id);
    float* onorm = buf(norm_id);
    #pragma unroll
    for (int i = 0; i < 4; i++) {
        float inv = 1.0f / fmaxf(sqrtf(ss[i]), 1e-12f);
        size_t rb = (size_t)(R + ty * 4 + i) * DOUT + colb;
        #pragma unroll
        for (int c = 0; c < CPT; c++) {
            oraw[rb + c]  = o[i][c];
            onorm[rb + c] = o[i][c] * inv;
        }
    }
}

// ---------------------------------------------------------------------------
// Final scoring: one warp per batch element.
// all_emb = [E0(64) | N1(64) | N2(32) | N3(16)]   (176 dims)
// ---------------------------------------------------------------------------
__global__ void final_score(const int* __restrict__ users,
                            const int* __restrict__ pos,
                            const int* __restrict__ neg,
                            float* __restrict__ out) {
    int t    = blockIdx.x * blockDim.x + threadIdx.x;
    int w    = t >> 5;
    int lane = t & 31;
    if (w >= BB) return;

    int u = users[w];
    int p = N_USERS + pos[w];
    int n = N_USERS + neg[w];

    float sp = 0.f, sn = 0.f;

    #pragma unroll
    for (int j = 0; j < 2; j++) {
        int k = j * 32 + lane;
        float au = g_E0[(size_t)u * 64 + k];
        float ap = g_E0[(size_t)p * 64 + k];
        float an = g_E0[(size_t)n * 64 + k];
        sp += au * ap; sn += au * an;
    }
    #pragma unroll
    for (int j = 0; j < 2; j++) {
        int k = j * 32 + lane;
        float au = g_N1[(size_t)u * 64 + k];
        float ap = g_N1[(size_t)p * 64 + k];
        float an = g_N1[(size_t)n * 64 + k];
        sp += au * ap; sn += au * an;
    }
    {
        float au = g_N2[(size_t)u * 32 + lane];
        float ap = g_N2[(size_t)p * 32 + lane];
        float an = g_N2[(size_t)n * 32 + lane];
        sp += au * ap; sn += au * an;
    }
    if (lane < 16) {
        float au = g_N3[(size_t)u * 16 + lane];
        float ap = g_N3[(size_t)p * 16 + lane];
        float an = g_N3[(size_t)n * 16 + lane];
        sp += au * ap; sn += au * an;
    }

    #pragma unroll
    for (int off = 16; off > 0; off >>= 1) {
        sp += __shfl_xor_sync(0xffffffffu, sp, off);
        sn += __shfl_xor_sync(0xffffffffu, sn, off);
    }
    if (lane == 0) {
        out[(size_t)w * 2 + 0] = sp;
        out[(size_t)w * 2 + 1] = sn;
    }
}

// ---------------------------------------------------------------------------
// Launch
// ---------------------------------------------------------------------------
extern "C" void kernel_launch(void* const* d_in, const int* in_sizes, int n_in,
                              void* d_out, int out_size) {
    const int*   users = (const int*)  d_in[0];
    const int*   pos   = (const int*)  d_in[1];
    const int*   neg   = (const int*)  d_in[2];
    const int*   rows  = (const int*)  d_in[3];
    const int*   cols  = (const int*)  d_in[4];
    const float* vals  = (const float*)d_in[5];
    const float* ue    = (const float*)d_in[6];
    const float* ee    = (const float*)d_in[7];
    const float* Wg0 = (const float*)d_in[8],  *bg0 = (const float*)d_in[9];
    const float* Wb0 = (const float*)d_in[10], *bb0 = (const float*)d_in[11];
    const float* Wg1 = (const float*)d_in[12], *bg1 = (const float*)d_in[13];
    const float* Wb1 = (const float*)d_in[14], *bb1 = (const float*)d_in[15];
    const float* Wg2 = (const float*)d_in[16], *bg2 = (const float*)d_in[17];
    const float* Wb2 = (const float*)d_in[18], *bb2 = (const float*)d_in[19];
    float* out = (float*)d_out;

    // dynamic smem sizes
    const int smem0 = (2 * 64 * 65 + 2 * 64 * 64) * 4;  // 66048
    const int smem1 = (2 * 64 * 65 + 2 * 64 * 32) * 4;  // 49664
    const int smem2 = (2 * 64 * 33 + 2 * 32 * 16) * 4;  // 20992
    cudaFuncSetAttribute(transform_gemm<64, 64>,
                         cudaFuncAttributeMaxDynamicSharedMemorySize, smem0);
    cudaFuncSetAttribute(transform_gemm<64, 32>,
                         cudaFuncAttributeMaxDynamicSharedMemorySize, smem1);

    // init ego
    init_ego<<<(NN * 16 + 255) / 256, 256>>>((const float4*)ue, (const float4*)ee);

    // ---- CSR build ----
    zero_cnt<<<(NN + 255) / 256, 256>>>();
    hist<<<(EE + 255) / 256, 256>>>(rows);
    scan1<<<NBLK, 256>>>();
    scan2<<<1, 256>>>();
    scan3<<<(NN + 255) / 256, 256>>>();
    permute<<<(EE + 255) / 256, 256>>>(rows, cols, vals);

    const int spmm_blocks = (NN * 32 + 255) / 256;
    const int gemm_blocks = NN / 64;   // 3125 exact

    // ---- Layer 0: 64 -> 64 ----
    spmm_csr<64><<<spmm_blocks, 256>>>(0);
    transform_gemm<64, 64><<<gemm_blocks, 256, smem0>>>(0, Wg0, bg0, Wb0, bb0, 1, 3);

    // ---- Layer 1: 64 -> 32 ----
    spmm_csr<64><<<spmm_blocks, 256>>>(1);
    transform_gemm<64, 32><<<gemm_blocks, 256, smem1>>>(1, Wg1, bg1, Wb1, bb1, 2, 4);

    // ---- Layer 2: 32 -> 16 ----
    spmm_csr<32><<<spmm_blocks, 256>>>(2);
    transform_gemm<32, 16><<<gemm_blocks, 256, smem2>>>(2, Wg2, bg2, Wb2, bb2, 1, 5);

    // ---- Final scoring ----
    final_score<<<(BB * 32 + 255) / 256, 256>>>(users, pos, neg, out);
}

// round 7
// speedup vs baseline: 2.3602x; 1.0831x over previous
#include <cuda_runtime.h>

#define N_USERS 50000
#define N_ENT   150000
#define NN      200000   // N_USERS + N_ENT
#define EE      2000000
#define BB      8192
#define CHUNK   1024
#define NBLK    ((NN + CHUNK - 1) / CHUNK)   // 196

// ---------------------------------------------------------------------------
// Device-global scratch
// ---------------------------------------------------------------------------
__device__ float g_A [(size_t)NN * 64];  // raw ego after layer 0
__device__ float g_Bu[(size_t)NN * 32];  // raw ego after layer 1
__device__ float g_N1[(size_t)NN * 64];  // l2norm after layer 0
__device__ float g_N2[(size_t)NN * 32];  // l2norm after layer 1
__device__ float g_N3[(size_t)NN * 16];  // l2norm after layer 2

// CSR structures
__device__ int    g_cnt[NN];         // histogram, then permute cursor
__device__ int    g_rowptr[NN + 1];
__device__ int    g_bsum[NBLK];
__device__ int    g_boff[NBLK];
__device__ float2 g_edges[EE];       // packed (col_as_float_bits, val)

__device__ __forceinline__ float leaky(float x) {
    return x >= 0.f ? x : 0.01f * x;
}

// packed f32x2 helpers
__device__ __forceinline__ unsigned long long pk2(float x, float y) {
    unsigned long long r;
    asm("mov.b64 %0, {%1, %2};" : "=l"(r) : "f"(x), "f"(y));
    return r;
}
__device__ __forceinline__ void upk2(unsigned long long v, float& x, float& y) {
    asm("mov.b64 {%0, %1}, %2;" : "=f"(x), "=f"(y) : "l"(v));
}
__device__ __forceinline__ unsigned long long f2fma(unsigned long long a,
                                                    unsigned long long b,
                                                    unsigned long long c) {
    unsigned long long d;
    asm("fma.rn.f32x2 %0, %1, %2, %3;" : "=l"(d) : "l"(a), "l"(b), "l"(c));
    return d;
}

// ---------------------------------------------------------------------------
// CSR build
// ---------------------------------------------------------------------------
__global__ void zero_cnt() {
    int i = blockIdx.x * blockDim.x + threadIdx.x;
    if (i < NN) g_cnt[i] = 0;
}

__global__ void hist(const int* __restrict__ rows) {
    int e = blockIdx.x * blockDim.x + threadIdx.x;
    if (e < EE) atomicAdd(&g_cnt[rows[e]], 1);
}

__global__ void scan1() {
    __shared__ int sh[256];
    int b = blockIdx.x, t = threadIdx.x;
    int base = b * CHUNK + t * 4;
    int v[4]; int s = 0;
    #pragma unroll
    for (int j = 0; j < 4; j++) {
        int idx = base + j;
        v[j] = (idx < NN) ? g_cnt[idx] : 0;
        s += v[j];
    }
    sh[t] = s;
    __syncthreads();
    for (int off = 1; off < 256; off <<= 1) {
        int x = (t >= off) ? sh[t - off] : 0;
        __syncthreads();
        sh[t] += x;
        __syncthreads();
    }
    int excl = sh[t] - s;
    #pragma unroll
    for (int j = 0; j < 4; j++) {
        int idx = base + j;
        if (idx < NN) g_rowptr[idx] = excl;
        excl += v[j];
    }
    if (t == 255) g_bsum[b] = sh[255];
}

__global__ void scan2() {
    __shared__ int sh[256];
    int t = threadIdx.x;
    int v = (t < NBLK) ? g_bsum[t] : 0;
    sh[t] = v;
    __syncthreads();
    for (int off = 1; off < 256; off <<= 1) {
        int x = (t >= off) ? sh[t - off] : 0;
        __syncthreads();
        sh[t] += x;
        __syncthreads();
    }
    if (t < NBLK) g_boff[t] = sh[t] - v;
}

__global__ void scan3() {
    int i = blockIdx.x * blockDim.x + threadIdx.x;
    if (i < NN) {
        int r = g_rowptr[i] + g_boff[i / CHUNK];
        g_rowptr[i] = r;
        g_cnt[i]    = r;
    }
    if (i == 0) g_rowptr[NN] = EE;
}

__global__ void permute(const int* __restrict__ rows, const int* __restrict__ cols,
                        const float* __restrict__ vals) {
    int e = blockIdx.x * blockDim.x + threadIdx.x;
    if (e < EE) {
        int r = rows[e];
        int p = atomicAdd(&g_cnt[r], 1);
        g_edges[p] = make_float2(__int_as_float(cols[e]), vals[e]);
    }
}

// ---------------------------------------------------------------------------
// Fused layer: per 64-node block
//   Phase A (warp = 8 nodes): side = sum val*ego[col]  (CSR gather)
//                             sA1 = ego + side ; sA2 = ego * side   (smem)
//   Phase B (16x16 GEMM): out = leaky(sA1@Wg+bg) + leaky(sA2@Wb+bb)
//                         write raw (optional) + l2norm
// ego source: ego_id==0 -> split (ue, ee) harness inputs; else device buffer.
// ---------------------------------------------------------------------------
__device__ float* rawbuf(int id) { return id == 1 ? g_A : g_Bu; }
__device__ float* normbuf(int id) { return id == 3 ? g_N1 : (id == 4 ? g_N2 : g_N3); }

template <int DIN, int DOUT, bool WRITE_RAW>
__global__ void fused_layer(int ego_id,
                            const float* __restrict__ ue, const float* __restrict__ ee,
                            const float* __restrict__ Wg, const float* __restrict__ bg,
                            const float* __restrict__ Wb, const float* __restrict__ bb,
                            int raw_id, int norm_id) {
    extern __shared__ float sm[];
    constexpr int LDA = DIN + 1;
    float* sA1 = sm;
    float* sA2 = sA1 + 64 * LDA;
    float* sWg = sA2 + 64 * LDA;
    float* sWb = sWg + DIN * DOUT;

    int tid  = threadIdx.x;
    int base = blockIdx.x * 64;

    // ego source pointers (unified addressing: node c -> su+c*DIN if c<N_USERS,
    // else se+(c-N_USERS)*DIN; for internal buffers se = su + N_USERS*DIN)
    const float* su;
    const float* se;
    if (ego_id == 0)      { su = ue; se = ee; }
    else                  { const float* p = rawbuf(ego_id); su = p; se = p + (size_t)N_USERS * DIN; }

    // stage weights
    for (int i = tid; i < DIN * DOUT; i += 256) { sWg[i] = Wg[i]; sWb[i] = Wb[i]; }

    // ---- Phase A: CSR gather, build A-tiles in smem ----
    int w    = tid >> 5;
    int lane = tid & 31;

    #pragma unroll 1
    for (int j = 0; j < 8; j++) {
        int n  = base + w * 8 + j;
        int s0 = g_rowptr[n];
        int s1 = g_rowptr[n + 1];

        if (DIN == 64) {
            float2 acc = make_float2(0.f, 0.f);
            for (int e0 = s0; e0 < s1; e0 += 32) {
                int m = min(32, s1 - e0);
                float2 ev = make_float2(0.f, 0.f);
                if (lane < m) ev = g_edges[e0 + lane];
                for (int jj = 0; jj < m; jj++) {
                    int   c = __shfl_sync(0xffffffffu, __float_as_int(ev.x), jj);
                    float v = __shfl_sync(0xffffffffu, ev.y, jj);
                    const float* src = (c < N_USERS) ? su + (size_t)c * 64
                                                     : se + (size_t)(c - N_USERS) * 64;
                    float2 g = ((const float2*)src)[lane];
                    acc.x += v * g.x;
                    acc.y += v * g.y;
                }
            }
            const float* eg = (n < N_USERS) ? su + (size_t)n * 64
                                            : se + (size_t)(n - N_USERS) * 64;
            float2 e = ((const float2*)eg)[lane];
            int lr = w * 8 + j;
            sA1[lr * LDA + 2 * lane]     = e.x + acc.x;
            sA1[lr * LDA + 2 * lane + 1] = e.y + acc.y;
            sA2[lr * LDA + 2 * lane]     = e.x * acc.x;
            sA2[lr * LDA + 2 * lane + 1] = e.y * acc.y;
        } else {  // DIN == 32
            float acc = 0.f;
            for (int e0 = s0; e0 < s1; e0 += 32) {
                int m = min(32, s1 - e0);
                float2 ev = make_float2(0.f, 0.f);
                if (lane < m) ev = g_edges[e0 + lane];
                for (int jj = 0; jj < m; jj++) {
                    int   c = __shfl_sync(0xffffffffu, __float_as_int(ev.x), jj);
                    float v = __shfl_sync(0xffffffffu, ev.y, jj);
                    const float* src = (c < N_USERS) ? su + (size_t)c * 32
                                                     : se + (size_t)(c - N_USERS) * 32;
                    acc += v * src[lane];
                }
            }
            const float* eg = (n < N_USERS) ? su + (size_t)n * 32
                                            : se + (size_t)(n - N_USERS) * 32;
            float e = eg[lane];
            int lr = w * 8 + j;
            sA1[lr * LDA + lane] = e + acc;
            sA2[lr * LDA + lane] = e * acc;
        }
    }
    __syncthreads();

    // ---- Phase B: GEMM ----
    int ty = tid >> 4, tx = tid & 15;
    constexpr int CPT = DOUT / 16;
    int colb = tx * CPT;

    float o[4][CPT];
    float ss[4] = {0.f, 0.f, 0.f, 0.f};

    if (CPT >= 2) {
        constexpr int C2 = (CPT >= 2) ? CPT / 2 : 1;
        unsigned long long accg[4][C2], accb[4][C2];
        #pragma unroll
        for (int c2 = 0; c2 < C2; c2++) {
            unsigned long long vg = pk2(bg[colb + 2 * c2], bg[colb + 2 * c2 + 1]);
            unsigned long long vb = pk2(bb[colb + 2 * c2], bb[colb + 2 * c2 + 1]);
            #pragma unroll
            for (int i = 0; i < 4; i++) { accg[i][c2] = vg; accb[i][c2] = vb; }
        }
        #pragma unroll 4
        for (int k = 0; k < DIN; k++) {
            unsigned long long pa1[4], pa2[4];
            #pragma unroll
            for (int i = 0; i < 4; i++) {
                float a1 = sA1[(ty * 4 + i) * LDA + k];
                float a2 = sA2[(ty * 4 + i) * LDA + k];
                pa1[i] = pk2(a1, a1);
                pa2[i] = pk2(a2, a2);
            }
            #pragma unroll
            for (int c2 = 0; c2 < C2; c2++) {
                unsigned long long wg = *(const unsigned long long*)(sWg + k * DOUT + colb + 2 * c2);
                unsigned long long wb = *(const unsigned long long*)(sWb + k * DOUT + colb + 2 * c2);
                #pragma unroll
                for (int i = 0; i < 4; i++) {
                    accg[i][c2] = f2fma(pa1[i], wg, accg[i][c2]);
                    accb[i][c2] = f2fma(pa2[i], wb, accb[i][c2]);
                }
            }
        }
        #pragma unroll
        for (int i = 0; i < 4; i++) {
            #pragma unroll
            for (int c2 = 0; c2 < C2; c2++) {
                float g0, g1, b0, b1;
                upk2(accg[i][c2], g0, g1);
                upk2(accb[i][c2], b0, b1);
                float x0 = leaky(g0) + leaky(b0);
                float x1 = leaky(g1) + leaky(b1);
                o[i][2 * c2]     = x0;
                o[i][2 * c2 + 1] = x1;
                ss[i] += x0 * x0 + x1 * x1;
            }
        }
    } else {
        float accg[4], accb[4];
        float big = bg[colb], bib = bb[colb];
        #pragma unroll
        for (int i = 0; i < 4; i++) { accg[i] = big; accb[i] = bib; }
        #pragma unroll 4
        for (int k = 0; k < DIN; k++) {
            float wgv = sWg[k * DOUT + colb];
            float wbv = sWb[k * DOUT + colb];
            #pragma unroll
            for (int i = 0; i < 4; i++) {
                accg[i] += sA1[(ty * 4 + i) * LDA + k] * wgv;
                accb[i] += sA2[(ty * 4 + i) * LDA + k] * wbv;
            }
        }
        #pragma unroll
        for (int i = 0; i < 4; i++) {
            float x = leaky(accg[i]) + leaky(accb[i]);
            o[i][0] = x;
            ss[i] += x * x;
        }
    }

    #pragma unroll
    for (int off = 8; off > 0; off >>= 1) {
        #pragma unroll
        for (int i = 0; i < 4; i++)
            ss[i] += __shfl_xor_sync(0xffffffffu, ss[i], off, 16);
    }

    float* oraw  = rawbuf(raw_id);
    float* onorm = normbuf(norm_id);
    #pragma unroll
    for (int i = 0; i < 4; i++) {
        float inv = 1.0f / fmaxf(sqrtf(ss[i]), 1e-12f);
        size_t rb = (size_t)(base + ty * 4 + i) * DOUT + colb;
        #pragma unroll
        for (int c = 0; c < CPT; c++) {
            if (WRITE_RAW) oraw[rb + c] = o[i][c];
            onorm[rb + c] = o[i][c] * inv;
        }
    }
}

// ---------------------------------------------------------------------------
// Final scoring: one warp per batch element.
// all_emb = [ego0(64) | N1(64) | N2(32) | N3(16)]  (176)
// ego0 comes straight from ue/ee.
// ---------------------------------------------------------------------------
__global__ void final_score(const int* __restrict__ users,
                            const int* __restrict__ pos,
                            const int* __restrict__ neg,
                            const float* __restrict__ ue,
                            const float* __restrict__ ee,
                            float* __restrict__ out) {
    int t    = blockIdx.x * blockDim.x + threadIdx.x;
    int w    = t >> 5;
    int lane = t & 31;
    if (w >= BB) return;

    int u  = users[w];
    int pe = pos[w];           // entity index
    int ne = neg[w];
    int p  = N_USERS + pe;     // global node index
    int n  = N_USERS + ne;

    float sp = 0.f, sn = 0.f;

    #pragma unroll
    for (int j = 0; j < 2; j++) {
        int k = j * 32 + lane;
        float au = ue[(size_t)u  * 64 + k];
        float ap = ee[(size_t)pe * 64 + k];
        float an = ee[(size_t)ne * 64 + k];
        sp += au * ap; sn += au * an;
    }
    #pragma unroll
    for (int j = 0; j < 2; j++) {
        int k = j * 32 + lane;
        float au = g_N1[(size_t)u * 64 + k];
        float ap = g_N1[(size_t)p * 64 + k];
        float an = g_N1[(size_t)n * 64 + k];
        sp += au * ap; sn += au * an;
    }
    {
        float au = g_N2[(size_t)u * 32 + lane];
        float ap = g_N2[(size_t)p * 32 + lane];
        float an = g_N2[(size_t)n * 32 + lane];
        sp += au * ap; sn += au * an;
    }
    if (lane < 16) {
        float au = g_N3[(size_t)u * 16 + lane];
        float ap = g_N3[(size_t)p * 16 + lane];
        float an = g_N3[(size_t)n * 16 + lane];
        sp += au * ap; sn += au * an;
    }

    #pragma unroll
    for (int off = 16; off > 0; off >>= 1) {
        sp += __shfl_xor_sync(0xffffffffu, sp, off);
        sn += __shfl_xor_sync(0xffffffffu, sn, off);
    }
    if (lane == 0) {
        out[(size_t)w * 2 + 0] = sp;
        out[(size_t)w * 2 + 1] = sn;
    }
}

// ---------------------------------------------------------------------------
// Launch
// ---------------------------------------------------------------------------
extern "C" void kernel_launch(void* const* d_in, const int* in_sizes, int n_in,
                              void* d_out, int out_size) {
    const int*   users = (const int*)  d_in[0];
    const int*   pos   = (const int*)  d_in[1];
    const int*   neg   = (const int*)  d_in[2];
    const int*   rows  = (const int*)  d_in[3];
    const int*   cols  = (const int*)  d_in[4];
    const float* vals  = (const float*)d_in[5];
    const float* ue    = (const float*)d_in[6];
    const float* ee    = (const float*)d_in[7];
    const float* Wg0 = (const float*)d_in[8],  *bg0 = (const float*)d_in[9];
    const float* Wb0 = (const float*)d_in[10], *bb0 = (const float*)d_in[11];
    const float* Wg1 = (const float*)d_in[12], *bg1 = (const float*)d_in[13];
    const float* Wb1 = (const float*)d_in[14], *bb1 = (const float*)d_in[15];
    const float* Wg2 = (const float*)d_in[16], *bg2 = (const float*)d_in[17];
    const float* Wb2 = (const float*)d_in[18], *bb2 = (const float*)d_in[19];
    float* out = (float*)d_out;

    const int smem0 = (2 * 64 * 65 + 2 * 64 * 64) * 4;  // 66048
    const int smem1 = (2 * 64 * 65 + 2 * 64 * 32) * 4;  // 49664
    const int smem2 = (2 * 64 * 33 + 2 * 32 * 16) * 4;  // 20992
    cudaFuncSetAttribute((const void*)fused_layer<64, 64, true>,
                         cudaFuncAttributeMaxDynamicSharedMemorySize, smem0);
    cudaFuncSetAttribute((const void*)fused_layer<64, 32, true>,
                         cudaFuncAttributeMaxDynamicSharedMemorySize, smem1);

    // ---- CSR build ----
    zero_cnt<<<(NN + 255) / 256, 256>>>();
    hist<<<(EE + 255) / 256, 256>>>(rows);
    scan1<<<NBLK, 256>>>();
    scan2<<<1, 256>>>();
    scan3<<<(NN + 255) / 256, 256>>>();
    permute<<<(EE + 255) / 256, 256>>>(rows, cols, vals);

    const int gemm_blocks = NN / 64;   // 3125 exact

    // ---- Layer 0: 64 -> 64 (ego: ue/ee split; raw -> g_A, norm -> g_N1) ----
    fused_layer<64, 64, true><<<gemm_blocks, 256, smem0>>>(
        0, ue, ee, Wg0, bg0, Wb0, bb0, 1, 3);

    // ---- Layer 1: 64 -> 32 (ego: g_A; raw -> g_Bu, norm -> g_N2) ----
    fused_layer<64, 32, true><<<gemm_blocks, 256, smem1>>>(
        1, ue, ee, Wg1, bg1, Wb1, bb1, 2, 4);

    // ---- Layer 2: 32 -> 16 (ego: g_Bu; norm -> g_N3, no raw) ----
    fused_layer<32, 16, false><<<gemm_blocks, 256, smem2>>>(
        2, ue, ee, Wg2, bg2, Wb2, bb2, 1, 5);

    // ---- Final scoring ----
    final_score<<<(BB * 32 + 255) / 256, 256>>>(users, pos, neg, ue, ee, out);
}